// round 14
// baseline (speedup 1.0000x reference)
#include <cuda_runtime.h>
#include <cuda_fp16.h>
#include <cstdint>
#include <math.h>

// Problem constants
#define HIDDEN   2048
#define NH       32
#define NKV      4
#define HD       128
#define BB       2
#define SS       2048
#define BTOK     (BB * SS)              // 4096
#define QKV_DIM  ((NH + 2 * NKV) * HD)  // 5120
#define ATTN_DIM (NH * HD)              // 4096
#define K_OFF    (NH * HD)              // 4096
#define V_OFF    (NH * HD + NKV * HD)   // 4608
#define QSCALE   0.08838834764831843f   // 1/sqrt(128)
#define L2E6_64  0.311430758193f        // log2(1e6)/64

// ------------------------------------------------------------
// Scratch (device globals; no runtime allocation allowed)
// ------------------------------------------------------------
__device__ float g_qkv[(size_t)BTOK * QKV_DIM];              // fp32 qkv proj
__device__ __half g_hh[(size_t)BTOK * HIDDEN];               // hidden fp16
__device__ __half g_wq[(size_t)QKV_DIM * HIDDEN];            // w_qkv fp16
__device__ __half g_wo[(size_t)HIDDEN * ATTN_DIM];           // w_o fp16
__device__ __half g_qh[(size_t)BTOK * NH * HD];              // Q fp16 (normed+roped+scaled)
__device__ __half g_kh[(size_t)BTOK * NKV * HD];             // K fp16 (normed+roped)
__device__ __half g_vh[(size_t)BTOK * NKV * HD];             // V fp16
__device__ __half g_ah[(size_t)BTOK * ATTN_DIM];             // attn out fp16

// ------------------------------------------------------------
// helpers
// ------------------------------------------------------------
__device__ __forceinline__ uint32_t smem_u32(const void* p) {
    uint32_t a;
    asm("{ .reg .u64 t; cvta.to.shared.u64 t, %1; cvt.u32.u64 %0, t; }" : "=r"(a) : "l"(p));
    return a;
}
__device__ __forceinline__ uint32_t pack2h(float x, float y) {
    uint32_t h;
    asm("cvt.rn.f16x2.f32 %0, %1, %2;" : "=r"(h) : "f"(y), "f"(x));
    return h;
}
__device__ __forceinline__ void ldm4(uint32_t addr, uint32_t& r0, uint32_t& r1,
                                     uint32_t& r2, uint32_t& r3) {
    asm volatile("ldmatrix.sync.aligned.m8n8.x4.shared.b16 {%0,%1,%2,%3}, [%4];"
                 : "=r"(r0), "=r"(r1), "=r"(r2), "=r"(r3) : "r"(addr));
}
__device__ __forceinline__ void ldm4t(uint32_t addr, uint32_t& r0, uint32_t& r1,
                                      uint32_t& r2, uint32_t& r3) {
    asm volatile("ldmatrix.sync.aligned.m8n8.x4.trans.shared.b16 {%0,%1,%2,%3}, [%4];"
                 : "=r"(r0), "=r"(r1), "=r"(r2), "=r"(r3) : "r"(addr));
}
__device__ __forceinline__ void mma_f16(float* c, const uint32_t* a, const uint32_t* b) {
    asm volatile(
        "mma.sync.aligned.m16n8k16.row.col.f32.f16.f16.f32 "
        "{%0,%1,%2,%3}, {%4,%5,%6,%7}, {%8,%9}, {%0,%1,%2,%3};"
        : "+f"(c[0]), "+f"(c[1]), "+f"(c[2]), "+f"(c[3])
        : "r"(a[0]), "r"(a[1]), "r"(a[2]), "r"(a[3]), "r"(b[0]), "r"(b[1]));
}
__device__ __forceinline__ void cp16(uint32_t dst, const void* src) {
    asm volatile("cp.async.cg.shared.global [%0], [%1], 16;" :: "r"(dst), "l"(src));
}
#define CP_COMMIT() asm volatile("cp.async.commit_group;" ::: "memory")
#define CP_WAIT0()  asm volatile("cp.async.wait_group 0;" ::: "memory")
#define CP_WAIT1()  asm volatile("cp.async.wait_group 1;" ::: "memory")

// ------------------------------------------------------------
// fused conversion pass (fp32 -> fp16) over all three inputs
// ------------------------------------------------------------
__global__ __launch_bounds__(256) void cvt_all(
    const float* __restrict__ x0, __half* __restrict__ h0, int n0,
    const float* __restrict__ x1, __half* __restrict__ h1, int n1,
    const float* __restrict__ x2, __half* __restrict__ h2, int n2)
{
    int i = blockIdx.x * blockDim.x + threadIdx.x;
    const float* x;
    __half* h;
    if (i < n0) { x = x0; h = h0; }
    else if (i < n0 + n1) { i -= n0; x = x1; h = h1; }
    else if (i < n0 + n1 + n2) { i -= n0 + n1; x = x2; h = h2; }
    else return;
    float4 v = ((const float4*)x)[i];
    ((uint2*)h)[i] = make_uint2(pack2h(v.x, v.y), pack2h(v.z, v.w));
}

// ------------------------------------------------------------
// single-pass fp16 tensor-core GEMM (NT): C = A[M,K]*B[N,K]^T
// 128x128x32 block tile, 4 warps (2x2), warp tile 64x64, 2 CTAs/SM
// ------------------------------------------------------------
#define SROW 80                        // 32 f16 = 64B + 16 pad
#define GTILE_B (128 * SROW)           // 10240
#define STAGE1_B (2 * GTILE_B)         // 20480 (A, B)
#define GEMM1_SMEM (2 * STAGE1_B)      // 40960

__global__ __launch_bounds__(128, 2) void gemm_tc1(
    const __half* __restrict__ A, const __half* __restrict__ B,
    float* __restrict__ C, int M, int N, int K)
{
    extern __shared__ char smc[];
    uint32_t smb = smem_u32(smc);
    int tid = threadIdx.x, lane = tid & 31, wid = tid >> 5;
    int warpM = wid >> 1, warpN = wid & 1;
    int bm = blockIdx.y * 128, bn = blockIdx.x * 128;

    int g8 = lane >> 3, r8 = lane & 7;
    uint32_t a_off = (uint32_t)(((g8 & 1) * 8 + r8) * SROW + (g8 >> 1) * 16);
    uint32_t b_off = (uint32_t)(((g8 >> 1) * 8 + r8) * SROW + (g8 & 1) * 16);

    auto stage_load = [&](int kb, int buf) {
        uint32_t base = smb + buf * STAGE1_B;
        int k0 = kb * 32;
#pragma unroll
        for (int i = 0; i < 4; i++) {
            int idx = i * 128 + tid;
            int row = idx >> 2, c4 = idx & 3;
            cp16(base + (uint32_t)(row * SROW + c4 * 16),
                 A + (size_t)(bm + row) * K + k0 + c4 * 8);
        }
#pragma unroll
        for (int i = 0; i < 4; i++) {
            int idx = i * 128 + tid;
            int row = idx >> 2, c4 = idx & 3;
            cp16(base + GTILE_B + (uint32_t)(row * SROW + c4 * 16),
                 B + (size_t)(bn + row) * K + k0 + c4 * 8);
        }
    };

    float acc[4][8][4];
#pragma unroll
    for (int mt = 0; mt < 4; mt++)
#pragma unroll
        for (int nt = 0; nt < 8; nt++)
#pragma unroll
            for (int e = 0; e < 4; e++) acc[mt][nt][e] = 0.f;

    stage_load(0, 0);
    CP_COMMIT();

    int nkb = K / 32, buf = 0;
    for (int kb = 0; kb < nkb; kb++) {
        if (kb + 1 < nkb) {
            stage_load(kb + 1, buf ^ 1);
            CP_COMMIT();
            CP_WAIT1();
        } else {
            CP_WAIT0();
        }
        __syncthreads();

        uint32_t base = smb + buf * STAGE1_B;
        uint32_t a_b = base + (uint32_t)(warpM * 64) * SROW + a_off;
        uint32_t b_b = base + GTILE_B + (uint32_t)(warpN * 64) * SROW + b_off;

#pragma unroll
        for (int ks = 0; ks < 2; ks++) {
            uint32_t koff = (uint32_t)(ks * 32);
            uint32_t Bf[8][2];
#pragma unroll
            for (int ntp = 0; ntp < 4; ntp++) {
                uint32_t r0, r1, r2, r3;
                ldm4(b_b + (uint32_t)(ntp * 16 * SROW) + koff, r0, r1, r2, r3);
                Bf[2 * ntp][0] = r0; Bf[2 * ntp][1] = r1;
                Bf[2 * ntp + 1][0] = r2; Bf[2 * ntp + 1][1] = r3;
            }
#pragma unroll
            for (int mt = 0; mt < 4; mt++) {
                uint32_t Af[4];
                ldm4(a_b + (uint32_t)(mt * 16 * SROW) + koff, Af[0], Af[1], Af[2], Af[3]);
#pragma unroll
                for (int nt = 0; nt < 8; nt++)
                    mma_f16(acc[mt][nt], Af, Bf[nt]);
            }
        }
        __syncthreads();
        buf ^= 1;
    }

    int erow = lane >> 2;
    int ecol = (lane & 3) * 2;
#pragma unroll
    for (int mt = 0; mt < 4; mt++) {
#pragma unroll
        for (int nt = 0; nt < 8; nt++) {
            int row0 = bm + warpM * 64 + mt * 16 + erow;
            int col = bn + warpN * 64 + nt * 8 + ecol;
            *(float2*)(C + (size_t)row0 * N + col) = make_float2(acc[mt][nt][0], acc[mt][nt][1]);
            *(float2*)(C + (size_t)(row0 + 8) * N + col) = make_float2(acc[mt][nt][2], acc[mt][nt][3]);
        }
    }
}

// ------------------------------------------------------------
// Fused RMSNorm + RoPE + convert: Q/K/V -> single fp16 (Q pre-scaled)
// ------------------------------------------------------------
__global__ __launch_bounds__(256) void norm_rope_split(
    const int* __restrict__ positions,
    const float* __restrict__ qw, const float* __restrict__ kw)
{
    const int NG = NH + 2 * NKV;  // 40
    int warp = (blockIdx.x * blockDim.x + threadIdx.x) >> 5;
    int lane = threadIdx.x & 31;
    if (warp >= BTOK * NG) return;
    int gidx = warp % NG;
    int tok = warp / NG;

    if (gidx < NH + NKV) {
        bool isQ = gidx < NH;
        const float* w = isQ ? qw : kw;
        int off = isQ ? gidx * HD : K_OFF + (gidx - NH) * HD;
        const float* x = g_qkv + (size_t)tok * QKV_DIM + off;

        float xa = x[lane], xb = x[lane + 32], xc = x[lane + 64], xd = x[lane + 96];
        float ss = xa * xa + xb * xb + xc * xc + xd * xd;
#pragma unroll
        for (int o = 16; o; o >>= 1) ss += __shfl_xor_sync(0xffffffffu, ss, o);
        float rr = rsqrtf(ss * (1.f / 128.f) + 1e-6f);
        xa *= rr * w[lane];
        xb *= rr * w[lane + 32];
        xc *= rr * w[lane + 64];
        xd *= rr * w[lane + 96];

        float pos = (float)positions[tok];
        float inv1 = exp2f(-(float)lane * L2E6_64);
        float inv2 = exp2f(-(float)(lane + 32) * L2E6_64);
        float s1, c1, s2, c2;
        sincosf(pos * inv1, &s1, &c1);
        sincosf(pos * inv2, &s2, &c2);

        float y0 = xa * c1 - xc * s1;
        float y1 = xb * c2 - xd * s2;
        float y2 = xc * c1 + xa * s1;
        float y3 = xd * c2 + xb * s2;

        if (isQ) {
            size_t o = ((size_t)tok * NH + gidx) * HD;
            g_qh[o + lane]      = __float2half_rn(y0 * QSCALE);
            g_qh[o + lane + 32] = __float2half_rn(y1 * QSCALE);
            g_qh[o + lane + 64] = __float2half_rn(y2 * QSCALE);
            g_qh[o + lane + 96] = __float2half_rn(y3 * QSCALE);
        } else {
            size_t o = ((size_t)tok * NKV + (gidx - NH)) * HD;
            g_kh[o + lane]      = __float2half_rn(y0);
            g_kh[o + lane + 32] = __float2half_rn(y1);
            g_kh[o + lane + 64] = __float2half_rn(y2);
            g_kh[o + lane + 96] = __float2half_rn(y3);
        }
    } else {
        int vh = gidx - NH - NKV;
        const float* x = g_qkv + (size_t)tok * QKV_DIM + V_OFF + vh * HD;
        size_t o = ((size_t)tok * NKV + vh) * HD;
#pragma unroll
        for (int j = 0; j < 4; j++) {
            int c = lane + 32 * j;
            g_vh[o + c] = __float2half_rn(x[c]);
        }
    }
}

// ------------------------------------------------------------
// Tensor-core causal flash attention, single-pass fp16
// CTA = 128 q rows x 1 head, 8 warps; KV tiles of 64, double buffer
// 2 CTAs/SM (regs <=128, smem 102KB); LPT scheduling
// ------------------------------------------------------------
#define FA_BM 128
#define FA_BN 64
#define FROW 272                 // 128 f16 = 256B + 16 pad
#define QTILE (128 * FROW)       // 34816
#define KVTILE (64 * FROW)       // 17408
#define SQ 0
#define SKV QTILE
#define KVSTAGE (2 * KVTILE)     // 34816 (K, V)
#define FA_SMEM (QTILE + 2 * KVSTAGE)   // 104448

__global__ __launch_bounds__(256, 2) void attn_tc()
{
    extern __shared__ char smc[];
    uint32_t smb = smem_u32(smc);
    int tid = threadIdx.x;
    int lane = tid & 31;
    int wid = tid >> 5;
    int qtile = gridDim.x - 1 - blockIdx.x;   // LPT: longest CTAs first
    int h = blockIdx.y;
    int b = blockIdx.z;
    int kvh = h >> 3;
    int q0 = qtile * FA_BM;

    int g8 = lane >> 3, r8 = lane & 7;
    uint32_t a_off = (uint32_t)(((g8 & 1) * 8 + r8) * FROW + (g8 >> 1) * 16);
    uint32_t b_off = (uint32_t)(((g8 >> 1) * 8 + r8) * FROW + (g8 & 1) * 16);

    // Q tile via cp.async (pre-scaled fp16)
#pragma unroll
    for (int i = 0; i < 8; i++) {
        int c = tid + i * 256;            // 2048 chunks: 128 rows x 16
        int row = c >> 4, c4 = c & 15;
        size_t src = ((size_t)(b * SS + q0 + row) * NH + h) * HD + c4 * 8;
        cp16(smb + SQ + (uint32_t)(row * FROW + c4 * 16), g_qh + src);
    }
    CP_COMMIT();

    auto kvload = [&](int t, int kbuf) {
        uint32_t base = smb + SKV + kbuf * KVSTAGE;
#pragma unroll
        for (int i = 0; i < 4; i++) {
            int c = tid + i * 256;        // 1024 chunks: 64 rows x 16
            int row = c >> 4, c4 = c & 15;
            size_t src = ((size_t)(b * SS + t * FA_BN + row) * NKV + kvh) * HD + c4 * 8;
            uint32_t doff = (uint32_t)(row * FROW + c4 * 16);
            cp16(base + doff, g_kh + src);
            cp16(base + KVTILE + doff, g_vh + src);
        }
    };

    kvload(0, 0);
    CP_COMMIT();

    float m0 = -1e30f, m1 = -1e30f, lsum0 = 0.f, lsum1 = 0.f;
    float co[16][4];
#pragma unroll
    for (int nf = 0; nf < 16; nf++)
#pragma unroll
        for (int e = 0; e < 4; e++) co[nf][e] = 0.f;

    int ntiles = 2 * qtile + 2;
    int kbuf = 0;
    for (int t = 0; t < ntiles; t++) {
        if (t + 1 < ntiles) {
            kvload(t + 1, kbuf ^ 1);
            CP_COMMIT();
            CP_WAIT1();
        } else {
            CP_WAIT0();
        }
        __syncthreads();

        int kv0 = t * FA_BN;
        bool skip = (kv0 > q0 + wid * 16 + 15);   // warp tile fully masked
        if (!skip) {
            uint32_t base = smb + SKV + kbuf * KVSTAGE;
            uint32_t qrow = smb + SQ + (uint32_t)(wid * 16) * FROW + a_off;

            // ---- S = Q K^T (single pass, Q frags from smem) ----
            float cs[4][2][4];
#pragma unroll
            for (int nb = 0; nb < 4; nb++)
#pragma unroll
                for (int f = 0; f < 2; f++)
#pragma unroll
                    for (int e = 0; e < 4; e++) cs[nb][f][e] = 0.f;

#pragma unroll
            for (int ks = 0; ks < 8; ks++) {
                uint32_t koff = (uint32_t)(ks * 32);
                uint32_t qf[4];
                ldm4(qrow + koff, qf[0], qf[1], qf[2], qf[3]);
#pragma unroll
                for (int nb = 0; nb < 4; nb++) {
                    uint32_t nboff = (uint32_t)(nb * 16) * FROW + koff;
                    uint32_t kf[4];
                    ldm4(base + nboff + b_off, kf[0], kf[1], kf[2], kf[3]);
                    mma_f16(cs[nb][0], qf, kf);
                    mma_f16(cs[nb][1], qf, kf + 2);
                }
            }

            // ---- causal mask (only top-two kv tiles can clip) ----
            if (t >= 2 * qtile) {
                int row0 = q0 + wid * 16 + (lane >> 2);
#pragma unroll
                for (int nb = 0; nb < 4; nb++)
#pragma unroll
                    for (int f = 0; f < 2; f++)
#pragma unroll
                        for (int e = 0; e < 4; e++) {
                            int col = kv0 + nb * 16 + f * 8 + 2 * (lane & 3) + (e & 1);
                            int row = row0 + ((e >> 1) ? 8 : 0);
                            if (col > row) cs[nb][f][e] = -1e30f;
                        }
            }

            // ---- online softmax ----
            float mt0 = -1e30f, mt1 = -1e30f;
#pragma unroll
            for (int nb = 0; nb < 4; nb++)
#pragma unroll
                for (int f = 0; f < 2; f++) {
                    mt0 = fmaxf(mt0, fmaxf(cs[nb][f][0], cs[nb][f][1]));
                    mt1 = fmaxf(mt1, fmaxf(cs[nb][f][2], cs[nb][f][3]));
                }
            mt0 = fmaxf(mt0, __shfl_xor_sync(0xffffffffu, mt0, 1));
            mt0 = fmaxf(mt0, __shfl_xor_sync(0xffffffffu, mt0, 2));
            mt1 = fmaxf(mt1, __shfl_xor_sync(0xffffffffu, mt1, 1));
            mt1 = fmaxf(mt1, __shfl_xor_sync(0xffffffffu, mt1, 2));
            float mn0 = fmaxf(m0, mt0);
            float mn1 = fmaxf(m1, mt1);
            float corr0 = __expf(m0 - mn0);
            float corr1 = __expf(m1 - mn1);
            float ps0 = 0.f, ps1 = 0.f;
#pragma unroll
            for (int nb = 0; nb < 4; nb++)
#pragma unroll
                for (int f = 0; f < 2; f++) {
                    cs[nb][f][0] = __expf(cs[nb][f][0] - mn0);
                    cs[nb][f][1] = __expf(cs[nb][f][1] - mn0);
                    cs[nb][f][2] = __expf(cs[nb][f][2] - mn1);
                    cs[nb][f][3] = __expf(cs[nb][f][3] - mn1);
                    ps0 += cs[nb][f][0] + cs[nb][f][1];
                    ps1 += cs[nb][f][2] + cs[nb][f][3];
                }
            ps0 += __shfl_xor_sync(0xffffffffu, ps0, 1);
            ps0 += __shfl_xor_sync(0xffffffffu, ps0, 2);
            ps1 += __shfl_xor_sync(0xffffffffu, ps1, 1);
            ps1 += __shfl_xor_sync(0xffffffffu, ps1, 2);
            lsum0 = lsum0 * corr0 + ps0;
            lsum1 = lsum1 * corr1 + ps1;
            m0 = mn0; m1 = mn1;
#pragma unroll
            for (int nf = 0; nf < 16; nf++) {
                co[nf][0] *= corr0; co[nf][1] *= corr0;
                co[nf][2] *= corr1; co[nf][3] *= corr1;
            }

            // ---- O += P V (single pass, P packed to fp16) ----
#pragma unroll
            for (int ks = 0; ks < 4; ks++) {
                uint32_t ph[4];
                ph[0] = pack2h(cs[ks][0][0], cs[ks][0][1]);
                ph[1] = pack2h(cs[ks][0][2], cs[ks][0][3]);
                ph[2] = pack2h(cs[ks][1][0], cs[ks][1][1]);
                ph[3] = pack2h(cs[ks][1][2], cs[ks][1][3]);
                uint32_t krow = (uint32_t)(ks * 16) * FROW;
#pragma unroll
                for (int db = 0; db < 8; db++) {
                    uint32_t doff = krow + (uint32_t)(db * 32) + a_off;
                    uint32_t vf[4];
                    ldm4t(base + KVTILE + doff, vf[0], vf[1], vf[2], vf[3]);
                    mma_f16(co[2 * db], ph, vf);
                    mma_f16(co[2 * db + 1], ph, vf + 2);
                }
            }
        }
        __syncthreads();
        kbuf ^= 1;
    }

    // epilogue: normalize, write fp16 for O projection
    float inv0 = 1.f / lsum0;
    float inv1 = 1.f / lsum1;
    int row0 = b * SS + q0 + wid * 16 + (lane >> 2);
    int colb = h * HD + 2 * (lane & 3);
#pragma unroll
    for (int nf = 0; nf < 16; nf++) {
        int col = colb + nf * 8;
        *(uint32_t*)(g_ah + (size_t)row0 * ATTN_DIM + col) =
            pack2h(co[nf][0] * inv0, co[nf][1] * inv0);
        *(uint32_t*)(g_ah + (size_t)(row0 + 8) * ATTN_DIM + col) =
            pack2h(co[nf][2] * inv1, co[nf][3] * inv1);
    }
}

// ------------------------------------------------------------
// launch
// ------------------------------------------------------------
extern "C" void kernel_launch(void* const* d_in, const int* in_sizes, int n_in,
                              void* d_out, int out_size)
{
    const float* hidden    = (const float*)d_in[0];
    const int*   positions = (const int*)d_in[1];
    const float* w_qkv     = (const float*)d_in[2];
    const float* w_o       = (const float*)d_in[3];
    const float* q_norm_w  = (const float*)d_in[4];
    const float* k_norm_w  = (const float*)d_in[5];
    float* out = (float*)d_out;

    float* qkv_buf;
    __half *hh, *wq, *wo, *ah;
    cudaGetSymbolAddress((void**)&qkv_buf, g_qkv);
    cudaGetSymbolAddress((void**)&hh, g_hh);
    cudaGetSymbolAddress((void**)&wq, g_wq);
    cudaGetSymbolAddress((void**)&wo, g_wo);
    cudaGetSymbolAddress((void**)&ah, g_ah);

    cudaFuncSetAttribute(gemm_tc1,
                         cudaFuncAttributeMaxDynamicSharedMemorySize, GEMM1_SMEM);
    cudaFuncSetAttribute(attn_tc,
                         cudaFuncAttributeMaxDynamicSharedMemorySize, FA_SMEM);

    // 0) fused fp32 -> fp16 conversion of all inputs
    {
        int n0 = BTOK * HIDDEN / 4;
        int n1 = QKV_DIM * HIDDEN / 4;
        int n2 = HIDDEN * ATTN_DIM / 4;
        int total = n0 + n1 + n2;
        cvt_all<<<(total + 255) / 256, 256>>>(hidden, hh, n0, w_qkv, wq, n1, w_o, wo, n2);
    }

    // 1) QKV projection (single-pass fp16, 128x128 tiles) -> fp32 g_qkv
    gemm_tc1<<<dim3(QKV_DIM / 128, BTOK / 128), 128, GEMM1_SMEM>>>(
        hh, wq, qkv_buf, BTOK, QKV_DIM, HIDDEN);

    // 2) RMSNorm + RoPE + fp16 convert
    {
        int total_warps = BTOK * (NH + 2 * NKV);
        norm_rope_split<<<(total_warps + 7) / 8, 256>>>(positions, q_norm_w, k_norm_w);
    }

    // 3) causal GQA flash attention (single-pass fp16, 2 CTAs/SM, LPT)
    attn_tc<<<dim3(SS / FA_BM, NH, BB), 256, FA_SMEM>>>();

    // 4) O projection (single-pass fp16, 128x128 tiles) -> fp32 out
    gemm_tc1<<<dim3(HIDDEN / 128, BTOK / 128), 128, GEMM1_SMEM>>>(
        ah, wo, out, BTOK, HIDDEN, ATTN_DIM);
}

// round 16
// speedup vs baseline: 1.0309x; 1.0309x over previous
#include <cuda_runtime.h>
#include <cuda_fp16.h>
#include <cstdint>
#include <math.h>

// Problem constants
#define HIDDEN   2048
#define NH       32
#define NKV      4
#define HD       128
#define BB       2
#define SS       2048
#define BTOK     (BB * SS)              // 4096
#define QKV_DIM  ((NH + 2 * NKV) * HD)  // 5120
#define ATTN_DIM (NH * HD)              // 4096
#define K_OFF    (NH * HD)              // 4096
#define V_OFF    (NH * HD + NKV * HD)   // 4608
#define QSCALE   0.08838834764831843f   // 1/sqrt(128)
#define L2E6_64  0.311430758193f        // log2(1e6)/64

// ------------------------------------------------------------
// Scratch (device globals; no runtime allocation allowed)
// ------------------------------------------------------------
__device__ __half g_qkv16[(size_t)BTOK * QKV_DIM];           // fp16 qkv proj
__device__ __half g_hh[(size_t)BTOK * HIDDEN];               // hidden fp16
__device__ __half g_wq[(size_t)QKV_DIM * HIDDEN];            // w_qkv fp16
__device__ __half g_wo[(size_t)HIDDEN * ATTN_DIM];           // w_o fp16
__device__ __half g_qh[(size_t)BTOK * NH * HD];              // Q fp16 (normed+roped+scaled)
__device__ __half g_kh[(size_t)BTOK * NKV * HD];             // K fp16 (normed+roped)
__device__ __half g_vh[(size_t)BTOK * NKV * HD];             // V fp16
__device__ __half g_ah[(size_t)BTOK * ATTN_DIM];             // attn out fp16

// ------------------------------------------------------------
// helpers
// ------------------------------------------------------------
__device__ __forceinline__ uint32_t smem_u32(const void* p) {
    uint32_t a;
    asm("{ .reg .u64 t; cvta.to.shared.u64 t, %1; cvt.u32.u64 %0, t; }" : "=r"(a) : "l"(p));
    return a;
}
__device__ __forceinline__ uint32_t pack2h(float x, float y) {
    uint32_t h;
    asm("cvt.rn.f16x2.f32 %0, %1, %2;" : "=r"(h) : "f"(y), "f"(x));
    return h;
}
__device__ __forceinline__ void ldm4(uint32_t addr, uint32_t& r0, uint32_t& r1,
                                     uint32_t& r2, uint32_t& r3) {
    asm volatile("ldmatrix.sync.aligned.m8n8.x4.shared.b16 {%0,%1,%2,%3}, [%4];"
                 : "=r"(r0), "=r"(r1), "=r"(r2), "=r"(r3) : "r"(addr));
}
__device__ __forceinline__ void ldm4t(uint32_t addr, uint32_t& r0, uint32_t& r1,
                                      uint32_t& r2, uint32_t& r3) {
    asm volatile("ldmatrix.sync.aligned.m8n8.x4.trans.shared.b16 {%0,%1,%2,%3}, [%4];"
                 : "=r"(r0), "=r"(r1), "=r"(r2), "=r"(r3) : "r"(addr));
}
__device__ __forceinline__ void mma_f16(float* c, const uint32_t* a, const uint32_t* b) {
    asm volatile(
        "mma.sync.aligned.m16n8k16.row.col.f32.f16.f16.f32 "
        "{%0,%1,%2,%3}, {%4,%5,%6,%7}, {%8,%9}, {%0,%1,%2,%3};"
        : "+f"(c[0]), "+f"(c[1]), "+f"(c[2]), "+f"(c[3])
        : "r"(a[0]), "r"(a[1]), "r"(a[2]), "r"(a[3]), "r"(b[0]), "r"(b[1]));
}
__device__ __forceinline__ void cp16(uint32_t dst, const void* src) {
    asm volatile("cp.async.cg.shared.global [%0], [%1], 16;" :: "r"(dst), "l"(src));
}
#define CP_COMMIT() asm volatile("cp.async.commit_group;" ::: "memory")
#define CP_WAIT0()  asm volatile("cp.async.wait_group 0;" ::: "memory")
#define CP_WAIT1()  asm volatile("cp.async.wait_group 1;" ::: "memory")

// ------------------------------------------------------------
// fused conversion pass (fp32 -> fp16) over all three inputs
// ------------------------------------------------------------
__global__ __launch_bounds__(256) void cvt_all(
    const float* __restrict__ x0, __half* __restrict__ h0, int n0,
    const float* __restrict__ x1, __half* __restrict__ h1, int n1,
    const float* __restrict__ x2, __half* __restrict__ h2, int n2)
{
    int i = blockIdx.x * blockDim.x + threadIdx.x;
    const float* x;
    __half* h;
    if (i < n0) { x = x0; h = h0; }
    else if (i < n0 + n1) { i -= n0; x = x1; h = h1; }
    else if (i < n0 + n1 + n2) { i -= n0 + n1; x = x2; h = h2; }
    else return;
    float4 v = ((const float4*)x)[i];
    ((uint2*)h)[i] = make_uint2(pack2h(v.x, v.y), pack2h(v.z, v.w));
}

// ------------------------------------------------------------
// single-pass fp16 tensor-core GEMM (NT): C = A[M,K]*B[N,K]^T
// 128x128x32 block tile, 4 warps (2x2), warp tile 64x64, 2 CTAs/SM
// templated output type: fp32 or fp16
// ------------------------------------------------------------
#define SROW 80                        // 32 f16 = 64B + 16 pad
#define GTILE_B (128 * SROW)           // 10240
#define STAGE1_B (2 * GTILE_B)         // 20480 (A, B)
#define GEMM1_SMEM (2 * STAGE1_B)      // 40960

template <bool HALF_OUT>
__global__ __launch_bounds__(128, 2) void gemm_tc1(
    const __half* __restrict__ A, const __half* __restrict__ B,
    void* __restrict__ Cv, int M, int N, int K)
{
    extern __shared__ char smc[];
    uint32_t smb = smem_u32(smc);
    int tid = threadIdx.x, lane = tid & 31, wid = tid >> 5;
    int warpM = wid >> 1, warpN = wid & 1;
    int bm = blockIdx.y * 128, bn = blockIdx.x * 128;

    int g8 = lane >> 3, r8 = lane & 7;
    uint32_t a_off = (uint32_t)(((g8 & 1) * 8 + r8) * SROW + (g8 >> 1) * 16);
    uint32_t b_off = (uint32_t)(((g8 >> 1) * 8 + r8) * SROW + (g8 & 1) * 16);

    auto stage_load = [&](int kb, int buf) {
        uint32_t base = smb + buf * STAGE1_B;
        int k0 = kb * 32;
#pragma unroll
        for (int i = 0; i < 4; i++) {
            int idx = i * 128 + tid;
            int row = idx >> 2, c4 = idx & 3;
            cp16(base + (uint32_t)(row * SROW + c4 * 16),
                 A + (size_t)(bm + row) * K + k0 + c4 * 8);
        }
#pragma unroll
        for (int i = 0; i < 4; i++) {
            int idx = i * 128 + tid;
            int row = idx >> 2, c4 = idx & 3;
            cp16(base + GTILE_B + (uint32_t)(row * SROW + c4 * 16),
                 B + (size_t)(bn + row) * K + k0 + c4 * 8);
        }
    };

    float acc[4][8][4];
#pragma unroll
    for (int mt = 0; mt < 4; mt++)
#pragma unroll
        for (int nt = 0; nt < 8; nt++)
#pragma unroll
            for (int e = 0; e < 4; e++) acc[mt][nt][e] = 0.f;

    stage_load(0, 0);
    CP_COMMIT();

    int nkb = K / 32, buf = 0;
    for (int kb = 0; kb < nkb; kb++) {
        if (kb + 1 < nkb) {
            stage_load(kb + 1, buf ^ 1);
            CP_COMMIT();
            CP_WAIT1();
        } else {
            CP_WAIT0();
        }
        __syncthreads();

        uint32_t base = smb + buf * STAGE1_B;
        uint32_t a_b = base + (uint32_t)(warpM * 64) * SROW + a_off;
        uint32_t b_b = base + GTILE_B + (uint32_t)(warpN * 64) * SROW + b_off;

#pragma unroll
        for (int ks = 0; ks < 2; ks++) {
            uint32_t koff = (uint32_t)(ks * 32);
            uint32_t Bf[8][2];
#pragma unroll
            for (int ntp = 0; ntp < 4; ntp++) {
                uint32_t r0, r1, r2, r3;
                ldm4(b_b + (uint32_t)(ntp * 16 * SROW) + koff, r0, r1, r2, r3);
                Bf[2 * ntp][0] = r0; Bf[2 * ntp][1] = r1;
                Bf[2 * ntp + 1][0] = r2; Bf[2 * ntp + 1][1] = r3;
            }
#pragma unroll
            for (int mt = 0; mt < 4; mt++) {
                uint32_t Af[4];
                ldm4(a_b + (uint32_t)(mt * 16 * SROW) + koff, Af[0], Af[1], Af[2], Af[3]);
#pragma unroll
                for (int nt = 0; nt < 8; nt++)
                    mma_f16(acc[mt][nt], Af, Bf[nt]);
            }
        }
        __syncthreads();
        buf ^= 1;
    }

    int erow = lane >> 2;
    int ecol = (lane & 3) * 2;
#pragma unroll
    for (int mt = 0; mt < 4; mt++) {
#pragma unroll
        for (int nt = 0; nt < 8; nt++) {
            int row0 = bm + warpM * 64 + mt * 16 + erow;
            int col = bn + warpN * 64 + nt * 8 + ecol;
            if (HALF_OUT) {
                __half* C = (__half*)Cv;
                *(uint32_t*)(C + (size_t)row0 * N + col) = pack2h(acc[mt][nt][0], acc[mt][nt][1]);
                *(uint32_t*)(C + (size_t)(row0 + 8) * N + col) = pack2h(acc[mt][nt][2], acc[mt][nt][3]);
            } else {
                float* C = (float*)Cv;
                *(float2*)(C + (size_t)row0 * N + col) = make_float2(acc[mt][nt][0], acc[mt][nt][1]);
                *(float2*)(C + (size_t)(row0 + 8) * N + col) = make_float2(acc[mt][nt][2], acc[mt][nt][3]);
            }
        }
    }
}

// ------------------------------------------------------------
// Fused RMSNorm + RoPE + convert (reads fp16 qkv)
// ------------------------------------------------------------
__global__ __launch_bounds__(256) void norm_rope_split(
    const int* __restrict__ positions,
    const float* __restrict__ qw, const float* __restrict__ kw)
{
    const int NG = NH + 2 * NKV;  // 40
    int warp = (blockIdx.x * blockDim.x + threadIdx.x) >> 5;
    int lane = threadIdx.x & 31;
    if (warp >= BTOK * NG) return;
    int gidx = warp % NG;
    int tok = warp / NG;

    if (gidx < NH + NKV) {
        bool isQ = gidx < NH;
        const float* w = isQ ? qw : kw;
        int off = isQ ? gidx * HD : K_OFF + (gidx - NH) * HD;
        const __half* x = g_qkv16 + (size_t)tok * QKV_DIM + off;

        float xa = __half2float(x[lane]);
        float xb = __half2float(x[lane + 32]);
        float xc = __half2float(x[lane + 64]);
        float xd = __half2float(x[lane + 96]);
        float ss = xa * xa + xb * xb + xc * xc + xd * xd;
#pragma unroll
        for (int o = 16; o; o >>= 1) ss += __shfl_xor_sync(0xffffffffu, ss, o);
        float rr = rsqrtf(ss * (1.f / 128.f) + 1e-6f);
        xa *= rr * w[lane];
        xb *= rr * w[lane + 32];
        xc *= rr * w[lane + 64];
        xd *= rr * w[lane + 96];

        float pos = (float)positions[tok];
        float inv1 = exp2f(-(float)lane * L2E6_64);
        float inv2 = exp2f(-(float)(lane + 32) * L2E6_64);
        float s1, c1, s2, c2;
        sincosf(pos * inv1, &s1, &c1);
        sincosf(pos * inv2, &s2, &c2);

        float y0 = xa * c1 - xc * s1;
        float y1 = xb * c2 - xd * s2;
        float y2 = xc * c1 + xa * s1;
        float y3 = xd * c2 + xb * s2;

        if (isQ) {
            size_t o = ((size_t)tok * NH + gidx) * HD;
            g_qh[o + lane]      = __float2half_rn(y0 * QSCALE);
            g_qh[o + lane + 32] = __float2half_rn(y1 * QSCALE);
            g_qh[o + lane + 64] = __float2half_rn(y2 * QSCALE);
            g_qh[o + lane + 96] = __float2half_rn(y3 * QSCALE);
        } else {
            size_t o = ((size_t)tok * NKV + (gidx - NH)) * HD;
            g_kh[o + lane]      = __float2half_rn(y0);
            g_kh[o + lane + 32] = __float2half_rn(y1);
            g_kh[o + lane + 64] = __float2half_rn(y2);
            g_kh[o + lane + 96] = __float2half_rn(y3);
        }
    } else {
        int vh = gidx - NH - NKV;
        const __half* x = g_qkv16 + (size_t)tok * QKV_DIM + V_OFF + vh * HD;
        __half* dst = g_vh + ((size_t)tok * NKV + vh) * HD;
        // straight fp16 copy: 32 lanes x 8 bytes = 256 bytes = 128 halves
        ((uint2*)dst)[lane] = ((const uint2*)x)[lane];
    }
}

// ------------------------------------------------------------
// Tensor-core causal flash attention (round-13 version)
// CTA = 128 q rows x 1 head, 8 warps; KV tiles of 128, double buffer
// Q fragments hoisted to registers; LPT scheduling
// ------------------------------------------------------------
#define FA_BM 128
#define FA_BN 128
#define FROW 272                 // 128 f16 = 256B + 16 pad
#define QTILE (128 * FROW)       // 34816
#define KVTILE (128 * FROW)      // 34816
#define SQ 0
#define SKV QTILE
#define KVSTAGE (2 * KVTILE)     // 69632 (K, V)
#define FA_SMEM (QTILE + 2 * KVSTAGE)   // 174080

__global__ __launch_bounds__(256, 1) void attn_tc()
{
    extern __shared__ char smc[];
    uint32_t smb = smem_u32(smc);
    int tid = threadIdx.x;
    int lane = tid & 31;
    int wid = tid >> 5;
    int qtile = gridDim.x - 1 - blockIdx.x;   // LPT: longest CTAs first
    int h = blockIdx.y;
    int b = blockIdx.z;
    int kvh = h >> 3;
    int q0 = qtile * FA_BM;

    int g8 = lane >> 3, r8 = lane & 7;
    uint32_t a_off = (uint32_t)(((g8 & 1) * 8 + r8) * FROW + (g8 >> 1) * 16);
    uint32_t b_off = (uint32_t)(((g8 >> 1) * 8 + r8) * FROW + (g8 & 1) * 16);

    // Q tile via cp.async (pre-scaled fp16)
#pragma unroll
    for (int i = 0; i < 8; i++) {
        int c = tid + i * 256;            // 2048 chunks: 128 rows x 16
        int row = c >> 4, c4 = c & 15;
        size_t src = ((size_t)(b * SS + q0 + row) * NH + h) * HD + c4 * 8;
        cp16(smb + SQ + (uint32_t)(row * FROW + c4 * 16), g_qh + src);
    }
    CP_COMMIT();

    auto kvload = [&](int t, int kbuf) {
        uint32_t base = smb + SKV + kbuf * KVSTAGE;
#pragma unroll
        for (int i = 0; i < 8; i++) {
            int c = tid + i * 256;        // 2048 chunks: 128 rows x 16
            int row = c >> 4, c4 = c & 15;
            size_t src = ((size_t)(b * SS + t * FA_BN + row) * NKV + kvh) * HD + c4 * 8;
            uint32_t doff = (uint32_t)(row * FROW + c4 * 16);
            cp16(base + doff, g_kh + src);
            cp16(base + KVTILE + doff, g_vh + src);
        }
    };

    kvload(0, 0);
    CP_COMMIT();

    // wait for Q (kv group still in flight), hoist Q frags to registers
    CP_WAIT1();
    __syncthreads();
    uint32_t qf[8][4];
    {
        uint32_t qrow = (uint32_t)(wid * 16) * FROW;
#pragma unroll
        for (int ks = 0; ks < 8; ks++)
            ldm4(smb + SQ + qrow + (uint32_t)(ks * 32) + a_off,
                 qf[ks][0], qf[ks][1], qf[ks][2], qf[ks][3]);
    }

    float m0 = -1e30f, m1 = -1e30f, lsum0 = 0.f, lsum1 = 0.f;
    float co[16][4];
#pragma unroll
    for (int nf = 0; nf < 16; nf++)
#pragma unroll
        for (int e = 0; e < 4; e++) co[nf][e] = 0.f;

    int ntiles = qtile + 1;
    int kbuf = 0;
    for (int t = 0; t < ntiles; t++) {
        if (t + 1 < ntiles) {
            kvload(t + 1, kbuf ^ 1);
            CP_COMMIT();
            CP_WAIT1();
        } else {
            CP_WAIT0();
        }
        __syncthreads();

        int kv0 = t * FA_BN;
        uint32_t base = smb + SKV + kbuf * KVSTAGE;

        // ---- S = Q K^T (single pass) ----
        float cs[8][2][4];
#pragma unroll
        for (int nb = 0; nb < 8; nb++)
#pragma unroll
            for (int f = 0; f < 2; f++)
#pragma unroll
                for (int e = 0; e < 4; e++) cs[nb][f][e] = 0.f;

#pragma unroll
        for (int ks = 0; ks < 8; ks++) {
            uint32_t koff = (uint32_t)(ks * 32);
#pragma unroll
            for (int nb = 0; nb < 8; nb++) {
                uint32_t nboff = (uint32_t)(nb * 16) * FROW + koff;
                uint32_t kf[4];
                ldm4(base + nboff + b_off, kf[0], kf[1], kf[2], kf[3]);
                mma_f16(cs[nb][0], qf[ks], kf);
                mma_f16(cs[nb][1], qf[ks], kf + 2);
            }
        }

        // ---- causal mask (diagonal tile only) ----
        if (t == qtile) {
            int row0 = q0 + wid * 16 + (lane >> 2);
#pragma unroll
            for (int nb = 0; nb < 8; nb++)
#pragma unroll
                for (int f = 0; f < 2; f++)
#pragma unroll
                    for (int e = 0; e < 4; e++) {
                        int col = kv0 + nb * 16 + f * 8 + 2 * (lane & 3) + (e & 1);
                        int row = row0 + ((e >> 1) ? 8 : 0);
                        if (col > row) cs[nb][f][e] = -1e30f;
                    }
        }

        // ---- online softmax ----
        float mt0 = -1e30f, mt1 = -1e30f;
#pragma unroll
        for (int nb = 0; nb < 8; nb++)
#pragma unroll
            for (int f = 0; f < 2; f++) {
                mt0 = fmaxf(mt0, fmaxf(cs[nb][f][0], cs[nb][f][1]));
                mt1 = fmaxf(mt1, fmaxf(cs[nb][f][2], cs[nb][f][3]));
            }
        mt0 = fmaxf(mt0, __shfl_xor_sync(0xffffffffu, mt0, 1));
        mt0 = fmaxf(mt0, __shfl_xor_sync(0xffffffffu, mt0, 2));
        mt1 = fmaxf(mt1, __shfl_xor_sync(0xffffffffu, mt1, 1));
        mt1 = fmaxf(mt1, __shfl_xor_sync(0xffffffffu, mt1, 2));
        float mn0 = fmaxf(m0, mt0);
        float mn1 = fmaxf(m1, mt1);
        float corr0 = __expf(m0 - mn0);
        float corr1 = __expf(m1 - mn1);
        float ps0 = 0.f, ps1 = 0.f;
#pragma unroll
        for (int nb = 0; nb < 8; nb++)
#pragma unroll
            for (int f = 0; f < 2; f++) {
                cs[nb][f][0] = __expf(cs[nb][f][0] - mn0);
                cs[nb][f][1] = __expf(cs[nb][f][1] - mn0);
                cs[nb][f][2] = __expf(cs[nb][f][2] - mn1);
                cs[nb][f][3] = __expf(cs[nb][f][3] - mn1);
                ps0 += cs[nb][f][0] + cs[nb][f][1];
                ps1 += cs[nb][f][2] + cs[nb][f][3];
            }
        ps0 += __shfl_xor_sync(0xffffffffu, ps0, 1);
        ps0 += __shfl_xor_sync(0xffffffffu, ps0, 2);
        ps1 += __shfl_xor_sync(0xffffffffu, ps1, 1);
        ps1 += __shfl_xor_sync(0xffffffffu, ps1, 2);
        lsum0 = lsum0 * corr0 + ps0;
        lsum1 = lsum1 * corr1 + ps1;
        m0 = mn0; m1 = mn1;
#pragma unroll
        for (int nf = 0; nf < 16; nf++) {
            co[nf][0] *= corr0; co[nf][1] *= corr0;
            co[nf][2] *= corr1; co[nf][3] *= corr1;
        }

        // ---- O += P V (single pass, P packed to fp16) ----
#pragma unroll
        for (int ks = 0; ks < 8; ks++) {
            uint32_t ph[4];
            ph[0] = pack2h(cs[ks][0][0], cs[ks][0][1]);
            ph[1] = pack2h(cs[ks][0][2], cs[ks][0][3]);
            ph[2] = pack2h(cs[ks][1][0], cs[ks][1][1]);
            ph[3] = pack2h(cs[ks][1][2], cs[ks][1][3]);
            uint32_t krow = (uint32_t)(ks * 16) * FROW;
#pragma unroll
            for (int db = 0; db < 8; db++) {
                uint32_t doff = krow + (uint32_t)(db * 32) + a_off;
                uint32_t vf[4];
                ldm4t(base + KVTILE + doff, vf[0], vf[1], vf[2], vf[3]);
                mma_f16(co[2 * db], ph, vf);
                mma_f16(co[2 * db + 1], ph, vf + 2);
            }
        }
        __syncthreads();
        kbuf ^= 1;
    }

    // epilogue: normalize, write fp16 for O projection
    float inv0 = 1.f / lsum0;
    float inv1 = 1.f / lsum1;
    int row0 = b * SS + q0 + wid * 16 + (lane >> 2);
    int colb = h * HD + 2 * (lane & 3);
#pragma unroll
    for (int nf = 0; nf < 16; nf++) {
        int col = colb + nf * 8;
        *(uint32_t*)(g_ah + (size_t)row0 * ATTN_DIM + col) =
            pack2h(co[nf][0] * inv0, co[nf][1] * inv0);
        *(uint32_t*)(g_ah + (size_t)(row0 + 8) * ATTN_DIM + col) =
            pack2h(co[nf][2] * inv1, co[nf][3] * inv1);
    }
}

// ------------------------------------------------------------
// launch
// ------------------------------------------------------------
extern "C" void kernel_launch(void* const* d_in, const int* in_sizes, int n_in,
                              void* d_out, int out_size)
{
    const float* hidden    = (const float*)d_in[0];
    const int*   positions = (const int*)d_in[1];
    const float* w_qkv     = (const float*)d_in[2];
    const float* w_o       = (const float*)d_in[3];
    const float* q_norm_w  = (const float*)d_in[4];
    const float* k_norm_w  = (const float*)d_in[5];
    float* out = (float*)d_out;

    __half *qkv16, *hh, *wq, *wo, *ah;
    cudaGetSymbolAddress((void**)&qkv16, g_qkv16);
    cudaGetSymbolAddress((void**)&hh, g_hh);
    cudaGetSymbolAddress((void**)&wq, g_wq);
    cudaGetSymbolAddress((void**)&wo, g_wo);
    cudaGetSymbolAddress((void**)&ah, g_ah);

    cudaFuncSetAttribute(gemm_tc1<true>,
                         cudaFuncAttributeMaxDynamicSharedMemorySize, GEMM1_SMEM);
    cudaFuncSetAttribute(gemm_tc1<false>,
                         cudaFuncAttributeMaxDynamicSharedMemorySize, GEMM1_SMEM);
    cudaFuncSetAttribute(attn_tc,
                         cudaFuncAttributeMaxDynamicSharedMemorySize, FA_SMEM);

    // 0) fused fp32 -> fp16 conversion of all inputs
    {
        int n0 = BTOK * HIDDEN / 4;
        int n1 = QKV_DIM * HIDDEN / 4;
        int n2 = HIDDEN * ATTN_DIM / 4;
        int total = n0 + n1 + n2;
        cvt_all<<<(total + 255) / 256, 256>>>(hidden, hh, n0, w_qkv, wq, n1, w_o, wo, n2);
    }

    // 1) QKV projection -> fp16 g_qkv16
    gemm_tc1<true><<<dim3(QKV_DIM / 128, BTOK / 128), 128, GEMM1_SMEM>>>(
        hh, wq, qkv16, BTOK, QKV_DIM, HIDDEN);

    // 2) RMSNorm + RoPE + fp16 convert
    {
        int total_warps = BTOK * (NH + 2 * NKV);
        norm_rope_split<<<(total_warps + 7) / 8, 256>>>(positions, q_norm_w, k_norm_w);
    }

    // 3) causal GQA flash attention (round-13 config, LPT)
    attn_tc<<<dim3(SS / FA_BM, NH, BB), 256, FA_SMEM>>>();

    // 4) O projection -> fp32 out
    gemm_tc1<false><<<dim3(HIDDEN / 128, BTOK / 128), 128, GEMM1_SMEM>>>(
        ah, wo, out, BTOK, HIDDEN, ATTN_DIM);
}

// round 17
// speedup vs baseline: 1.0730x; 1.0408x over previous
#include <cuda_runtime.h>
#include <cuda_fp16.h>
#include <cstdint>
#include <math.h>

// Problem constants
#define HIDDEN   2048
#define NH       32
#define NKV      4
#define HD       128
#define BB       2
#define SS       2048
#define BTOK     (BB * SS)              // 4096
#define QKV_DIM  ((NH + 2 * NKV) * HD)  // 5120
#define ATTN_DIM (NH * HD)              // 4096
#define K_OFF    (NH * HD)              // 4096
#define V_OFF    (NH * HD + NKV * HD)   // 4608
#define QSCALE   0.08838834764831843f   // 1/sqrt(128)
#define L2E6_64  0.311430758193f        // log2(1e6)/64

// ------------------------------------------------------------
// Scratch (device globals; no runtime allocation allowed)
// ------------------------------------------------------------
__device__ __half g_qkv16[(size_t)BTOK * QKV_DIM];           // fp16 qkv proj (V read in place)
__device__ __half g_hh[(size_t)BTOK * HIDDEN];               // hidden fp16
__device__ __half g_wq[(size_t)QKV_DIM * HIDDEN];            // w_qkv fp16
__device__ __half g_wo[(size_t)HIDDEN * ATTN_DIM];           // w_o fp16
__device__ __half g_qh[(size_t)BTOK * NH * HD];              // Q fp16 (normed+roped+scaled)
__device__ __half g_kh[(size_t)BTOK * NKV * HD];             // K fp16 (normed+roped)
__device__ __half g_ah[(size_t)BTOK * ATTN_DIM];             // attn out fp16

// ------------------------------------------------------------
// helpers
// ------------------------------------------------------------
__device__ __forceinline__ uint32_t smem_u32(const void* p) {
    uint32_t a;
    asm("{ .reg .u64 t; cvta.to.shared.u64 t, %1; cvt.u32.u64 %0, t; }" : "=r"(a) : "l"(p));
    return a;
}
__device__ __forceinline__ uint32_t pack2h(float x, float y) {
    uint32_t h;
    asm("cvt.rn.f16x2.f32 %0, %1, %2;" : "=r"(h) : "f"(y), "f"(x));
    return h;
}
__device__ __forceinline__ void ldm4(uint32_t addr, uint32_t& r0, uint32_t& r1,
                                     uint32_t& r2, uint32_t& r3) {
    asm volatile("ldmatrix.sync.aligned.m8n8.x4.shared.b16 {%0,%1,%2,%3}, [%4];"
                 : "=r"(r0), "=r"(r1), "=r"(r2), "=r"(r3) : "r"(addr));
}
__device__ __forceinline__ void ldm4t(uint32_t addr, uint32_t& r0, uint32_t& r1,
                                      uint32_t& r2, uint32_t& r3) {
    asm volatile("ldmatrix.sync.aligned.m8n8.x4.trans.shared.b16 {%0,%1,%2,%3}, [%4];"
                 : "=r"(r0), "=r"(r1), "=r"(r2), "=r"(r3) : "r"(addr));
}
__device__ __forceinline__ void mma_f16(float* c, const uint32_t* a, const uint32_t* b) {
    asm volatile(
        "mma.sync.aligned.m16n8k16.row.col.f32.f16.f16.f32 "
        "{%0,%1,%2,%3}, {%4,%5,%6,%7}, {%8,%9}, {%0,%1,%2,%3};"
        : "+f"(c[0]), "+f"(c[1]), "+f"(c[2]), "+f"(c[3])
        : "r"(a[0]), "r"(a[1]), "r"(a[2]), "r"(a[3]), "r"(b[0]), "r"(b[1]));
}
__device__ __forceinline__ void cp16(uint32_t dst, const void* src) {
    asm volatile("cp.async.cg.shared.global [%0], [%1], 16;" :: "r"(dst), "l"(src));
}
#define CP_COMMIT() asm volatile("cp.async.commit_group;" ::: "memory")
#define CP_WAIT0()  asm volatile("cp.async.wait_group 0;" ::: "memory")
#define CP_WAIT1()  asm volatile("cp.async.wait_group 1;" ::: "memory")

// ------------------------------------------------------------
// fused conversion pass (fp32 -> fp16) over all three inputs
// ------------------------------------------------------------
__global__ __launch_bounds__(256) void cvt_all(
    const float* __restrict__ x0, __half* __restrict__ h0, int n0,
    const float* __restrict__ x1, __half* __restrict__ h1, int n1,
    const float* __restrict__ x2, __half* __restrict__ h2, int n2)
{
    int i = blockIdx.x * blockDim.x + threadIdx.x;
    const float* x;
    __half* h;
    if (i < n0) { x = x0; h = h0; }
    else if (i < n0 + n1) { i -= n0; x = x1; h = h1; }
    else if (i < n0 + n1 + n2) { i -= n0 + n1; x = x2; h = h2; }
    else return;
    float4 v = ((const float4*)x)[i];
    ((uint2*)h)[i] = make_uint2(pack2h(v.x, v.y), pack2h(v.z, v.w));
}

// ------------------------------------------------------------
// single-pass fp16 tensor-core GEMM (NT): C = A[M,K]*B[N,K]^T
// 128x128x32 block tile, 4 warps (2x2), warp tile 64x64, 2 CTAs/SM
// 3-stage cp.async pipeline; templated output type
// ------------------------------------------------------------
#define SROW 80                        // 32 f16 = 64B + 16 pad
#define GTILE_B (128 * SROW)           // 10240
#define STAGE1_B (2 * GTILE_B)         // 20480 (A, B)
#define GEMM1_SMEM (3 * STAGE1_B)      // 61440 (3 stages)

template <bool HALF_OUT>
__global__ __launch_bounds__(128, 2) void gemm_tc1(
    const __half* __restrict__ A, const __half* __restrict__ B,
    void* __restrict__ Cv, int M, int N, int K)
{
    extern __shared__ char smc[];
    uint32_t smb = smem_u32(smc);
    int tid = threadIdx.x, lane = tid & 31, wid = tid >> 5;
    int warpM = wid >> 1, warpN = wid & 1;
    int bm = blockIdx.y * 128, bn = blockIdx.x * 128;

    int g8 = lane >> 3, r8 = lane & 7;
    uint32_t a_off = (uint32_t)(((g8 & 1) * 8 + r8) * SROW + (g8 >> 1) * 16);
    uint32_t b_off = (uint32_t)(((g8 >> 1) * 8 + r8) * SROW + (g8 & 1) * 16);

    auto stage_load = [&](int kb, int buf) {
        uint32_t base = smb + buf * STAGE1_B;
        int k0 = kb * 32;
#pragma unroll
        for (int i = 0; i < 4; i++) {
            int idx = i * 128 + tid;
            int row = idx >> 2, c4 = idx & 3;
            cp16(base + (uint32_t)(row * SROW + c4 * 16),
                 A + (size_t)(bm + row) * K + k0 + c4 * 8);
        }
#pragma unroll
        for (int i = 0; i < 4; i++) {
            int idx = i * 128 + tid;
            int row = idx >> 2, c4 = idx & 3;
            cp16(base + GTILE_B + (uint32_t)(row * SROW + c4 * 16),
                 B + (size_t)(bn + row) * K + k0 + c4 * 8);
        }
    };

    float acc[4][8][4];
#pragma unroll
    for (int mt = 0; mt < 4; mt++)
#pragma unroll
        for (int nt = 0; nt < 8; nt++)
#pragma unroll
            for (int e = 0; e < 4; e++) acc[mt][nt][e] = 0.f;

    // 3-stage prologue
    stage_load(0, 0);
    CP_COMMIT();
    stage_load(1, 1);
    CP_COMMIT();

    int nkb = K / 32;
    for (int kb = 0; kb < nkb; kb++) {
        if (kb + 1 < nkb) CP_WAIT1();   // group kb drained, kb+1 in flight
        else              CP_WAIT0();
        __syncthreads();

        if (kb + 2 < nkb) {
            stage_load(kb + 2, (kb + 2) % 3);
            CP_COMMIT();
        }

        uint32_t base = smb + (kb % 3) * STAGE1_B;
        uint32_t a_b = base + (uint32_t)(warpM * 64) * SROW + a_off;
        uint32_t b_b = base + GTILE_B + (uint32_t)(warpN * 64) * SROW + b_off;

#pragma unroll
        for (int ks = 0; ks < 2; ks++) {
            uint32_t koff = (uint32_t)(ks * 32);
            uint32_t Bf[8][2];
#pragma unroll
            for (int ntp = 0; ntp < 4; ntp++) {
                uint32_t r0, r1, r2, r3;
                ldm4(b_b + (uint32_t)(ntp * 16 * SROW) + koff, r0, r1, r2, r3);
                Bf[2 * ntp][0] = r0; Bf[2 * ntp][1] = r1;
                Bf[2 * ntp + 1][0] = r2; Bf[2 * ntp + 1][1] = r3;
            }
#pragma unroll
            for (int mt = 0; mt < 4; mt++) {
                uint32_t Af[4];
                ldm4(a_b + (uint32_t)(mt * 16 * SROW) + koff, Af[0], Af[1], Af[2], Af[3]);
#pragma unroll
                for (int nt = 0; nt < 8; nt++)
                    mma_f16(acc[mt][nt], Af, Bf[nt]);
            }
        }
    }

    int erow = lane >> 2;
    int ecol = (lane & 3) * 2;
#pragma unroll
    for (int mt = 0; mt < 4; mt++) {
#pragma unroll
        for (int nt = 0; nt < 8; nt++) {
            int row0 = bm + warpM * 64 + mt * 16 + erow;
            int col = bn + warpN * 64 + nt * 8 + ecol;
            if (HALF_OUT) {
                __half* C = (__half*)Cv;
                *(uint32_t*)(C + (size_t)row0 * N + col) = pack2h(acc[mt][nt][0], acc[mt][nt][1]);
                *(uint32_t*)(C + (size_t)(row0 + 8) * N + col) = pack2h(acc[mt][nt][2], acc[mt][nt][3]);
            } else {
                float* C = (float*)Cv;
                *(float2*)(C + (size_t)row0 * N + col) = make_float2(acc[mt][nt][0], acc[mt][nt][1]);
                *(float2*)(C + (size_t)(row0 + 8) * N + col) = make_float2(acc[mt][nt][2], acc[mt][nt][3]);
            }
        }
    }
}

// ------------------------------------------------------------
// Fused RMSNorm + RoPE (Q and K only; V stays in g_qkv16)
// ------------------------------------------------------------
__global__ __launch_bounds__(256) void norm_rope_split(
    const int* __restrict__ positions,
    const float* __restrict__ qw, const float* __restrict__ kw)
{
    const int NG = NH + NKV;  // 36
    int warp = (blockIdx.x * blockDim.x + threadIdx.x) >> 5;
    int lane = threadIdx.x & 31;
    if (warp >= BTOK * NG) return;
    int gidx = warp % NG;
    int tok = warp / NG;

    bool isQ = gidx < NH;
    const float* w = isQ ? qw : kw;
    int off = isQ ? gidx * HD : K_OFF + (gidx - NH) * HD;
    const __half* x = g_qkv16 + (size_t)tok * QKV_DIM + off;

    float xa = __half2float(x[lane]);
    float xb = __half2float(x[lane + 32]);
    float xc = __half2float(x[lane + 64]);
    float xd = __half2float(x[lane + 96]);
    float ss = xa * xa + xb * xb + xc * xc + xd * xd;
#pragma unroll
    for (int o = 16; o; o >>= 1) ss += __shfl_xor_sync(0xffffffffu, ss, o);
    float rr = rsqrtf(ss * (1.f / 128.f) + 1e-6f);
    xa *= rr * w[lane];
    xb *= rr * w[lane + 32];
    xc *= rr * w[lane + 64];
    xd *= rr * w[lane + 96];

    float pos = (float)positions[tok];
    float inv1 = exp2f(-(float)lane * L2E6_64);
    float inv2 = exp2f(-(float)(lane + 32) * L2E6_64);
    float s1, c1, s2, c2;
    sincosf(pos * inv1, &s1, &c1);
    sincosf(pos * inv2, &s2, &c2);

    float y0 = xa * c1 - xc * s1;
    float y1 = xb * c2 - xd * s2;
    float y2 = xc * c1 + xa * s1;
    float y3 = xd * c2 + xb * s2;

    if (isQ) {
        size_t o = ((size_t)tok * NH + gidx) * HD;
        g_qh[o + lane]      = __float2half_rn(y0 * QSCALE);
        g_qh[o + lane + 32] = __float2half_rn(y1 * QSCALE);
        g_qh[o + lane + 64] = __float2half_rn(y2 * QSCALE);
        g_qh[o + lane + 96] = __float2half_rn(y3 * QSCALE);
    } else {
        size_t o = ((size_t)tok * NKV + (gidx - NH)) * HD;
        g_kh[o + lane]      = __float2half_rn(y0);
        g_kh[o + lane + 32] = __float2half_rn(y1);
        g_kh[o + lane + 64] = __float2half_rn(y2);
        g_kh[o + lane + 96] = __float2half_rn(y3);
    }
}

// ------------------------------------------------------------
// Tensor-core causal flash attention (round-13 config)
// CTA = 128 q rows x 1 head, 8 warps; KV tiles of 128, double buffer
// Q fragments hoisted; V read directly from g_qkv16; LPT scheduling
// ------------------------------------------------------------
#define FA_BM 128
#define FA_BN 128
#define FROW 272                 // 128 f16 = 256B + 16 pad
#define QTILE (128 * FROW)       // 34816
#define KVTILE (128 * FROW)      // 34816
#define SQ 0
#define SKV QTILE
#define KVSTAGE (2 * KVTILE)     // 69632 (K, V)
#define FA_SMEM (QTILE + 2 * KVSTAGE)   // 174080

__global__ __launch_bounds__(256, 1) void attn_tc()
{
    extern __shared__ char smc[];
    uint32_t smb = smem_u32(smc);
    int tid = threadIdx.x;
    int lane = tid & 31;
    int wid = tid >> 5;
    int qtile = gridDim.x - 1 - blockIdx.x;   // LPT: longest CTAs first
    int h = blockIdx.y;
    int b = blockIdx.z;
    int kvh = h >> 3;
    int q0 = qtile * FA_BM;

    int g8 = lane >> 3, r8 = lane & 7;
    uint32_t a_off = (uint32_t)(((g8 & 1) * 8 + r8) * FROW + (g8 >> 1) * 16);
    uint32_t b_off = (uint32_t)(((g8 >> 1) * 8 + r8) * FROW + (g8 & 1) * 16);

    // Q tile via cp.async (pre-scaled fp16)
#pragma unroll
    for (int i = 0; i < 8; i++) {
        int c = tid + i * 256;            // 2048 chunks: 128 rows x 16
        int row = c >> 4, c4 = c & 15;
        size_t src = ((size_t)(b * SS + q0 + row) * NH + h) * HD + c4 * 8;
        cp16(smb + SQ + (uint32_t)(row * FROW + c4 * 16), g_qh + src);
    }
    CP_COMMIT();

    auto kvload = [&](int t, int kbuf) {
        uint32_t base = smb + SKV + kbuf * KVSTAGE;
#pragma unroll
        for (int i = 0; i < 8; i++) {
            int c = tid + i * 256;        // 2048 chunks: 128 rows x 16
            int row = c >> 4, c4 = c & 15;
            int tokr = b * SS + t * FA_BN + row;
            uint32_t doff = (uint32_t)(row * FROW + c4 * 16);
            cp16(base + doff,
                 g_kh + ((size_t)tokr * NKV + kvh) * HD + c4 * 8);
            cp16(base + KVTILE + doff,
                 g_qkv16 + (size_t)tokr * QKV_DIM + V_OFF + kvh * HD + c4 * 8);
        }
    };

    kvload(0, 0);
    CP_COMMIT();

    // wait for Q (kv group still in flight), hoist Q frags to registers
    CP_WAIT1();
    __syncthreads();
    uint32_t qf[8][4];
    {
        uint32_t qrow = (uint32_t)(wid * 16) * FROW;
#pragma unroll
        for (int ks = 0; ks < 8; ks++)
            ldm4(smb + SQ + qrow + (uint32_t)(ks * 32) + a_off,
                 qf[ks][0], qf[ks][1], qf[ks][2], qf[ks][3]);
    }

    float m0 = -1e30f, m1 = -1e30f, lsum0 = 0.f, lsum1 = 0.f;
    float co[16][4];
#pragma unroll
    for (int nf = 0; nf < 16; nf++)
#pragma unroll
        for (int e = 0; e < 4; e++) co[nf][e] = 0.f;

    int ntiles = qtile + 1;
    int kbuf = 0;
    for (int t = 0; t < ntiles; t++) {
        if (t + 1 < ntiles) {
            kvload(t + 1, kbuf ^ 1);
            CP_COMMIT();
            CP_WAIT1();
        } else {
            CP_WAIT0();
        }
        __syncthreads();

        int kv0 = t * FA_BN;
        uint32_t base = smb + SKV + kbuf * KVSTAGE;

        // ---- S = Q K^T (single pass) ----
        float cs[8][2][4];
#pragma unroll
        for (int nb = 0; nb < 8; nb++)
#pragma unroll
            for (int f = 0; f < 2; f++)
#pragma unroll
                for (int e = 0; e < 4; e++) cs[nb][f][e] = 0.f;

#pragma unroll
        for (int ks = 0; ks < 8; ks++) {
            uint32_t koff = (uint32_t)(ks * 32);
#pragma unroll
            for (int nb = 0; nb < 8; nb++) {
                uint32_t nboff = (uint32_t)(nb * 16) * FROW + koff;
                uint32_t kf[4];
                ldm4(base + nboff + b_off, kf[0], kf[1], kf[2], kf[3]);
                mma_f16(cs[nb][0], qf[ks], kf);
                mma_f16(cs[nb][1], qf[ks], kf + 2);
            }
        }

        // ---- causal mask (diagonal tile only) ----
        if (t == qtile) {
            int row0 = q0 + wid * 16 + (lane >> 2);
#pragma unroll
            for (int nb = 0; nb < 8; nb++)
#pragma unroll
                for (int f = 0; f < 2; f++)
#pragma unroll
                    for (int e = 0; e < 4; e++) {
                        int col = kv0 + nb * 16 + f * 8 + 2 * (lane & 3) + (e & 1);
                        int row = row0 + ((e >> 1) ? 8 : 0);
                        if (col > row) cs[nb][f][e] = -1e30f;
                    }
        }

        // ---- online softmax ----
        float mt0 = -1e30f, mt1 = -1e30f;
#pragma unroll
        for (int nb = 0; nb < 8; nb++)
#pragma unroll
            for (int f = 0; f < 2; f++) {
                mt0 = fmaxf(mt0, fmaxf(cs[nb][f][0], cs[nb][f][1]));
                mt1 = fmaxf(mt1, fmaxf(cs[nb][f][2], cs[nb][f][3]));
            }
        mt0 = fmaxf(mt0, __shfl_xor_sync(0xffffffffu, mt0, 1));
        mt0 = fmaxf(mt0, __shfl_xor_sync(0xffffffffu, mt0, 2));
        mt1 = fmaxf(mt1, __shfl_xor_sync(0xffffffffu, mt1, 1));
        mt1 = fmaxf(mt1, __shfl_xor_sync(0xffffffffu, mt1, 2));
        float mn0 = fmaxf(m0, mt0);
        float mn1 = fmaxf(m1, mt1);
        float corr0 = __expf(m0 - mn0);
        float corr1 = __expf(m1 - mn1);
        float ps0 = 0.f, ps1 = 0.f;
#pragma unroll
        for (int nb = 0; nb < 8; nb++)
#pragma unroll
            for (int f = 0; f < 2; f++) {
                cs[nb][f][0] = __expf(cs[nb][f][0] - mn0);
                cs[nb][f][1] = __expf(cs[nb][f][1] - mn0);
                cs[nb][f][2] = __expf(cs[nb][f][2] - mn1);
                cs[nb][f][3] = __expf(cs[nb][f][3] - mn1);
                ps0 += cs[nb][f][0] + cs[nb][f][1];
                ps1 += cs[nb][f][2] + cs[nb][f][3];
            }
        ps0 += __shfl_xor_sync(0xffffffffu, ps0, 1);
        ps0 += __shfl_xor_sync(0xffffffffu, ps0, 2);
        ps1 += __shfl_xor_sync(0xffffffffu, ps1, 1);
        ps1 += __shfl_xor_sync(0xffffffffu, ps1, 2);
        lsum0 = lsum0 * corr0 + ps0;
        lsum1 = lsum1 * corr1 + ps1;
        m0 = mn0; m1 = mn1;
#pragma unroll
        for (int nf = 0; nf < 16; nf++) {
            co[nf][0] *= corr0; co[nf][1] *= corr0;
            co[nf][2] *= corr1; co[nf][3] *= corr1;
        }

        // ---- O += P V (single pass, P packed to fp16) ----
#pragma unroll
        for (int ks = 0; ks < 8; ks++) {
            uint32_t ph[4];
            ph[0] = pack2h(cs[ks][0][0], cs[ks][0][1]);
            ph[1] = pack2h(cs[ks][0][2], cs[ks][0][3]);
            ph[2] = pack2h(cs[ks][1][0], cs[ks][1][1]);
            ph[3] = pack2h(cs[ks][1][2], cs[ks][1][3]);
            uint32_t krow = (uint32_t)(ks * 16) * FROW;
#pragma unroll
            for (int db = 0; db < 8; db++) {
                uint32_t doff = krow + (uint32_t)(db * 32) + a_off;
                uint32_t vf[4];
                ldm4t(base + KVTILE + doff, vf[0], vf[1], vf[2], vf[3]);
                mma_f16(co[2 * db], ph, vf);
                mma_f16(co[2 * db + 1], ph, vf + 2);
            }
        }
        __syncthreads();
        kbuf ^= 1;
    }

    // epilogue: normalize, write fp16 for O projection
    float inv0 = 1.f / lsum0;
    float inv1 = 1.f / lsum1;
    int row0 = b * SS + q0 + wid * 16 + (lane >> 2);
    int colb = h * HD + 2 * (lane & 3);
#pragma unroll
    for (int nf = 0; nf < 16; nf++) {
        int col = colb + nf * 8;
        *(uint32_t*)(g_ah + (size_t)row0 * ATTN_DIM + col) =
            pack2h(co[nf][0] * inv0, co[nf][1] * inv0);
        *(uint32_t*)(g_ah + (size_t)(row0 + 8) * ATTN_DIM + col) =
            pack2h(co[nf][2] * inv1, co[nf][3] * inv1);
    }
}

// ------------------------------------------------------------
// launch
// ------------------------------------------------------------
extern "C" void kernel_launch(void* const* d_in, const int* in_sizes, int n_in,
                              void* d_out, int out_size)
{
    const float* hidden    = (const float*)d_in[0];
    const int*   positions = (const int*)d_in[1];
    const float* w_qkv     = (const float*)d_in[2];
    const float* w_o       = (const float*)d_in[3];
    const float* q_norm_w  = (const float*)d_in[4];
    const float* k_norm_w  = (const float*)d_in[5];
    float* out = (float*)d_out;

    __half *qkv16, *hh, *wq, *wo, *ah;
    cudaGetSymbolAddress((void**)&qkv16, g_qkv16);
    cudaGetSymbolAddress((void**)&hh, g_hh);
    cudaGetSymbolAddress((void**)&wq, g_wq);
    cudaGetSymbolAddress((void**)&wo, g_wo);
    cudaGetSymbolAddress((void**)&ah, g_ah);

    cudaFuncSetAttribute(gemm_tc1<true>,
                         cudaFuncAttributeMaxDynamicSharedMemorySize, GEMM1_SMEM);
    cudaFuncSetAttribute(gemm_tc1<false>,
                         cudaFuncAttributeMaxDynamicSharedMemorySize, GEMM1_SMEM);
    cudaFuncSetAttribute(attn_tc,
                         cudaFuncAttributeMaxDynamicSharedMemorySize, FA_SMEM);

    // 0) fused fp32 -> fp16 conversion of all inputs
    {
        int n0 = BTOK * HIDDEN / 4;
        int n1 = QKV_DIM * HIDDEN / 4;
        int n2 = HIDDEN * ATTN_DIM / 4;
        int total = n0 + n1 + n2;
        cvt_all<<<(total + 255) / 256, 256>>>(hidden, hh, n0, w_qkv, wq, n1, w_o, wo, n2);
    }

    // 1) QKV projection -> fp16 g_qkv16
    gemm_tc1<true><<<dim3(QKV_DIM / 128, BTOK / 128), 128, GEMM1_SMEM>>>(
        hh, wq, qkv16, BTOK, QKV_DIM, HIDDEN);

    // 2) RMSNorm + RoPE (Q and K only)
    {
        int total_warps = BTOK * (NH + NKV);
        norm_rope_split<<<(total_warps + 7) / 8, 256>>>(positions, q_norm_w, k_norm_w);
    }

    // 3) causal GQA flash attention (V direct from g_qkv16, LPT)
    attn_tc<<<dim3(SS / FA_BM, NH, BB), 256, FA_SMEM>>>();

    // 4) O projection -> fp32 out
    gemm_tc1<false><<<dim3(HIDDEN / 128, BTOK / 128), 128, GEMM1_SMEM>>>(
        ah, wo, out, BTOK, HIDDEN, ATTN_DIM);
}